// round 12
// baseline (speedup 1.0000x reference)
#include <cuda_runtime.h>
#include <cstdint>

#define Bv 64
#define Kv 8
#define HWv 16384
#define HW4 4096
#define EPSF 1e-15f
#define LN2F 0.6931471805599453f
#define CHUNKS 32
#define NBLK1 (Bv * CHUNKS)     // 2048
#define TOT4 2097152            // (B*K*HW)/4

// scratch (no allocations allowed -> device globals)
__device__ float g_partial[NBLK1 * 72];  // per (b,chunk): 64 cross + 8 ent (log2 units)
__device__ int   g_inv[Bv * Kv];         // col -> source pred row
__device__ float g_cost[Bv];             // per-batch min assignment cost

__device__ __forceinline__ void cpa16(unsigned int dst, const void* src) {
    asm volatile("cp.async.cg.shared.global [%0], [%1], 16;\n" :: "r"(dst), "l"(src));
}
__device__ __forceinline__ void cpcommit() {
    asm volatile("cp.async.commit_group;\n");
}
template <int N> __device__ __forceinline__ void cpwait() {
    asm volatile("cp.async.wait_group %0;\n" :: "n"(N));
}

// ---------------------------------------------------------------------------
// Kernel 1: 128-thread CTAs (8/SM), depth-3 cp.async pipeline, log2, scalar FMA.
//   cross2[i][j] = sum_hw t_j * log2(p_i + eps)
//   ent2[j]      = sum_hw t_j * log2(t_j + eps)
// Block (b, chunk of 128 f4 per row); 4 stages of 32 f4.
// Phase A: log2-convert p in place (once/elem) + ent (row tid>>4, once/elem).
// Phase B: warp w owns 4x4 tile (it=w>>1, jt=w&1), lane = hw quad, scalar FFMA.
// ---------------------------------------------------------------------------
__global__ __launch_bounds__(128, 8) void k1(const float4* __restrict__ pred4,
                                             const float4* __restrict__ aug4) {
    __shared__ float4 sp[3][8][32];   // pred tiles (raw -> log2 in place)
    __shared__ float4 stt[3][8][32];  // aug tiles
    __shared__ float red[4][16];
    __shared__ float entw[4][2];

    const int bx = blockIdx.x;
    const int b = bx >> 5, chunk = bx & 31;
    const int tid = threadIdx.x;
    const int lrow = tid >> 4, lcol = tid & 15;   // load mapping: 8 rows x 16 thr

    const float4* pb = pred4 + (size_t)b * (Kv * HW4) + (size_t)lrow * HW4 + chunk * 128 + lcol;
    const float4* tb = aug4  + (size_t)b * (Kv * HW4) + (size_t)lrow * HW4 + chunk * 128 + lcol;

    const unsigned int dp0 = (unsigned int)__cvta_generic_to_shared(&sp[0][lrow][lcol]);
    const unsigned int dt0 = (unsigned int)__cvta_generic_to_shared(&stt[0][lrow][lcol]);
    const unsigned int bufstride = (unsigned int)((char*)&sp[1][0][0] - (char*)&sp[0][0][0]);

    // compute mapping: warp-exclusive 4x4 tile
    const int warp = tid >> 5, lane = tid & 31;
    const int it = warp >> 1, jt = warp & 1;

    float acc[4][4];
#pragma unroll
    for (int r = 0; r < 4; r++)
#pragma unroll
        for (int c = 0; c < 4; c++) acc[r][c] = 0.f;
    float entacc = 0.f;               // share of ent2[j = lrow]

    // prologue: stages 0 and 1 in flight
#pragma unroll
    for (int s0 = 0; s0 < 2; s0++) {
        const unsigned int off = s0 * bufstride;
        cpa16(dp0 + off, pb + s0 * 32);  cpa16(dp0 + off + 256, pb + s0 * 32 + 16);
        cpa16(dt0 + off, tb + s0 * 32);  cpa16(dt0 + off + 256, tb + s0 * 32 + 16);
        cpcommit();
    }

#pragma unroll
    for (int s = 0; s < 4; s++) {
        const int buf = s % 3;
        if (s + 2 < 4) {
            const int nb = (s + 2) % 3;
            const unsigned int off = nb * bufstride;
            cpa16(dp0 + off, pb + (s + 2) * 32);  cpa16(dp0 + off + 256, pb + (s + 2) * 32 + 16);
            cpa16(dt0 + off, tb + (s + 2) * 32);  cpa16(dt0 + off + 256, tb + (s + 2) * 32 + 16);
            cpcommit();
            cpwait<2>();
        } else if (s + 1 < 4) {
            cpwait<1>();
        } else {
            cpwait<0>();
        }
        __syncthreads();

        // ---- Phase A: log2-convert p in place + ent2 (each element once) ----
        {
            float4 p0 = sp[buf][lrow][lcol];
            float4 p1 = sp[buf][lrow][lcol + 16];
            p0.x = __log2f(p0.x + EPSF); p0.y = __log2f(p0.y + EPSF);
            p0.z = __log2f(p0.z + EPSF); p0.w = __log2f(p0.w + EPSF);
            p1.x = __log2f(p1.x + EPSF); p1.y = __log2f(p1.y + EPSF);
            p1.z = __log2f(p1.z + EPSF); p1.w = __log2f(p1.w + EPSF);
            sp[buf][lrow][lcol] = p0;
            sp[buf][lrow][lcol + 16] = p1;

            float4 t0 = stt[buf][lrow][lcol];
            float4 t1 = stt[buf][lrow][lcol + 16];
            entacc += t0.x * __log2f(t0.x + EPSF) + t0.y * __log2f(t0.y + EPSF)
                    + t0.z * __log2f(t0.z + EPSF) + t0.w * __log2f(t0.w + EPSF);
            entacc += t1.x * __log2f(t1.x + EPSF) + t1.y * __log2f(t1.y + EPSF)
                    + t1.z * __log2f(t1.z + EPSF) + t1.w * __log2f(t1.w + EPSF);
        }
        __syncthreads();

        // ---- Phase B: scalar-FMA cross products (low staging: bb[4] + one a) ----
        {
            float4 bb[4];
#pragma unroll
            for (int c = 0; c < 4; c++) bb[c] = stt[buf][4 * jt + c][lane];
#pragma unroll
            for (int r = 0; r < 4; r++) {
                const float4 a = sp[buf][4 * it + r][lane];
#pragma unroll
                for (int c = 0; c < 4; c++)
                    acc[r][c] += a.x * bb[c].x + a.y * bb[c].y
                               + a.z * bb[c].z + a.w * bb[c].w;
            }
        }
        __syncthreads();
    }

    // ---- deterministic reductions ----
#pragma unroll
    for (int r = 0; r < 4; r++)
#pragma unroll
        for (int c = 0; c < 4; c++) {
            float v = acc[r][c];
#pragma unroll
            for (int o = 16; o > 0; o >>= 1) v += __shfl_xor_sync(0xffffffffu, v, o);
            if (lane == 0) red[warp][r * 4 + c] = v;
        }
    {
        // lanes 0-15 hold row 2*warp, lanes 16-31 hold row 2*warp+1
        float v = entacc;
#pragma unroll
        for (int o = 8; o > 0; o >>= 1) v += __shfl_xor_sync(0xffffffffu, v, o);
        if (lane == 0)  entw[warp][0] = v;
        if (lane == 16) entw[warp][1] = v;
    }
    __syncthreads();

    if (tid < 64) {
        const int i = tid >> 3, j = tid & 7;
        const int w = (i >> 2) * 2 + (j >> 2);
        const int k = (i & 3) * 4 + (j & 3);
        g_partial[bx * 72 + tid] = red[w][k];
    } else if (tid < 72) {
        const int j = tid - 64;
        g_partial[bx * 72 + tid] = entw[j >> 1][j & 1];
    }
}

// ---------------------------------------------------------------------------
// Kernel 2: per batch — C[i][j] = ln2*(ent2[j] - cross2[i][j])/HW; exact
// assignment via suffix bitmask DP; forward greedy backtrack (smallest j on
// ties == lexicographically-first permutation, matching itertools argmin).
// ---------------------------------------------------------------------------
__global__ __launch_bounds__(128) void k2() {
    const int b = blockIdx.x, t = threadIdx.x;
    __shared__ float raw[72];
    __shared__ float C[8][8];
    __shared__ float g[256];

    if (t < 72) {
        float s = 0.f;
#pragma unroll
        for (int c = 0; c < CHUNKS; c++) s += g_partial[(b * CHUNKS + c) * 72 + t];
        raw[t] = s * (LN2F / (float)HWv);   // back to natural-log units
    }
    __syncthreads();
    if (t < 64) C[t >> 3][t & 7] = raw[64 + (t & 7)] - raw[t];
    if (t == 0) g[0] = 0.f;
    __syncthreads();

    for (int c = 1; c <= 8; c++) {
        const int rowi = 8 - c;
        for (int m = t; m < 256; m += 128) {
            if (__popc(m) == c) {
                float best = 3.4e38f;
#pragma unroll
                for (int j = 0; j < 8; j++)
                    if (m & (1 << j)) {
                        float v = g[m ^ (1 << j)] + C[rowi][j];
                        best = fminf(best, v);
                    }
                g[m] = best;
            }
        }
        __syncthreads();
    }

    if (t == 0) {
        g_cost[b] = g[255];
        int mask = 255;
        for (int r = 0; r < 8; r++) {
            float best = 3.4e38f;
            int bj = 0;
#pragma unroll
            for (int j = 0; j < 8; j++)
                if (mask & (1 << j)) {
                    float v = C[r][j] + g[mask ^ (1 << j)];
                    if (v < best) { best = v; bj = j; }
                }
            g_inv[b * 8 + bj] = r;   // output col bj sources pred row r
            mask ^= (1 << bj);
        }
    }
}

// ---------------------------------------------------------------------------
// Kernel 3: vectorized permuted copy with +1 realignment via shfl.
// out4[m] = (flat[4m-1], flat[4m], flat[4m+1], flat[4m+2]),  flat[-1] = loss.
// ---------------------------------------------------------------------------
__global__ __launch_bounds__(256) void k3(const float* __restrict__ pred,
                                          float* __restrict__ out) {
    if (blockIdx.x == TOT4 / 256) {
        if (threadIdx.x == 0) {
            const int u = Bv * Kv * HWv - 1;
            const int pl = u >> 14, pos = u & (HWv - 1);
            const int sr = (pl & ~7) + g_inv[pl];
            out[Bv * Kv * HWv] = pred[(size_t)sr * HWv + pos];
        }
        return;
    }
    const int mi = blockIdx.x * 256 + threadIdx.x;   // [0, TOT4)
    const int pm = mi >> 12;                         // plane = (4m)>>14
    const int q = mi & (HW4 - 1);
    const int src = (pm & ~7) + g_inv[pm];

    const float4* pred4 = (const float4*)pred;
    float4 v = pred4[(size_t)src * HW4 + q];

    float prev = __shfl_up_sync(0xffffffffu, v.w, 1);
    if ((threadIdx.x & 31) == 0) {
        if (mi == 0) {
            float ssum = 0.f;
#pragma unroll
            for (int bb = 0; bb < Bv; bb++) ssum += g_cost[bb];  // fixed order
            prev = ssum * (1.0f / (float)(Bv * Kv));
        } else {
            const int u = 4 * mi - 1;
            const int pl = u >> 14, pos = u & (HWv - 1);
            const int sr = (pl & ~7) + g_inv[pl];
            prev = pred[(size_t)sr * HWv + pos];
        }
    }
    float4 o4;
    o4.x = prev; o4.y = v.x; o4.z = v.y; o4.w = v.z;
    ((float4*)out)[mi] = o4;
}

extern "C" void kernel_launch(void* const* d_in, const int* in_sizes, int n_in,
                              void* d_out, int out_size) {
    const float* pred = (const float*)d_in[0];
    const float* aug  = (const float*)d_in[1];
    float* out = (float*)d_out;

    k1<<<NBLK1, 128>>>((const float4*)pred, (const float4*)aug);
    k2<<<Bv, 128>>>();
    k3<<<TOT4 / 256 + 1, 256>>>(pred, out);
}

// round 16
// speedup vs baseline: 1.0635x; 1.0635x over previous
#include <cuda_runtime.h>
#include <cstdint>

#define Bv 64
#define Kv 8
#define HWv 16384
#define HW4 4096
#define EPSF 1e-15f
#define LN2F 0.6931471805599453f
#define CHUNKS 32
#define NBLK1 (Bv * CHUNKS)     // 2048
#define TOT4 2097152            // (B*K*HW)/4

// scratch (no allocations allowed -> device globals)
__device__ float g_partial[NBLK1 * 72];  // per (b,chunk): 64 cross + 8 ent (log2 units)
__device__ int   g_inv[Bv * Kv];         // col -> source pred row (0..7)
__device__ float g_cost[Bv];             // per-batch min assignment cost

__device__ __forceinline__ void cpa16(unsigned int dst, const void* src) {
    asm volatile("cp.async.cg.shared.global [%0], [%1], 16;\n" :: "r"(dst), "l"(src));
}
__device__ __forceinline__ void cpcommit() {
    asm volatile("cp.async.commit_group;\n");
}
template <int N> __device__ __forceinline__ void cpwait() {
    asm volatile("cp.async.wait_group %0;\n" :: "n"(N));
}

// ---------------------------------------------------------------------------
// Kernel 1: 128-thread CTAs (8/SM), depth-3 cp.async pipeline, log2, scalar
// FMA, 2 barriers/stage (cp.async issue moved after the top barrier).
//   cross2[i][j] = sum_hw t_j * log2(p_i + eps)
//   ent2[j]      = sum_hw t_j * log2(t_j + eps)
// ---------------------------------------------------------------------------
__global__ __launch_bounds__(128, 8) void k1(const float4* __restrict__ pred4,
                                             const float4* __restrict__ aug4) {
    __shared__ float4 sp[3][8][32];   // pred tiles (raw -> log2 in place)
    __shared__ float4 stt[3][8][32];  // aug tiles
    __shared__ float red[4][16];
    __shared__ float entw[4][2];

    const int bx = blockIdx.x;
    const int b = bx >> 5, chunk = bx & 31;
    const int tid = threadIdx.x;
    const int lrow = tid >> 4, lcol = tid & 15;   // load mapping: 8 rows x 16 thr

    const float4* pb = pred4 + (size_t)b * (Kv * HW4) + (size_t)lrow * HW4 + chunk * 128 + lcol;
    const float4* tb = aug4  + (size_t)b * (Kv * HW4) + (size_t)lrow * HW4 + chunk * 128 + lcol;

    const unsigned int dp0 = (unsigned int)__cvta_generic_to_shared(&sp[0][lrow][lcol]);
    const unsigned int dt0 = (unsigned int)__cvta_generic_to_shared(&stt[0][lrow][lcol]);
    const unsigned int bufstride = (unsigned int)((char*)&sp[1][0][0] - (char*)&sp[0][0][0]);

    // compute mapping: warp-exclusive 4x4 tile
    const int warp = tid >> 5, lane = tid & 31;
    const int it = warp >> 1, jt = warp & 1;

    float acc[4][4];
#pragma unroll
    for (int r = 0; r < 4; r++)
#pragma unroll
        for (int c = 0; c < 4; c++) acc[r][c] = 0.f;
    float entacc = 0.f;               // share of ent2[j = lrow]

    // prologue: stages 0 and 1 in flight
#pragma unroll
    for (int s0 = 0; s0 < 2; s0++) {
        const unsigned int off = s0 * bufstride;
        cpa16(dp0 + off, pb + s0 * 32);  cpa16(dp0 + off + 256, pb + s0 * 32 + 16);
        cpa16(dt0 + off, tb + s0 * 32);  cpa16(dt0 + off + 256, tb + s0 * 32 + 16);
        cpcommit();
    }

#pragma unroll
    for (int s = 0; s < 4; s++) {
        const int buf = s % 3;
        if (s < 3) cpwait<1>(); else cpwait<0>();
        __syncthreads();   // all threads see buf s; also releases buf (s+2)%3 from last B

        if (s + 2 < 4) {   // issue stage s+2 into the buffer B just released
            const int nb = (s + 2) % 3;
            const unsigned int off = nb * bufstride;
            cpa16(dp0 + off, pb + (s + 2) * 32);  cpa16(dp0 + off + 256, pb + (s + 2) * 32 + 16);
            cpa16(dt0 + off, tb + (s + 2) * 32);  cpa16(dt0 + off + 256, tb + (s + 2) * 32 + 16);
            cpcommit();
        }

        // ---- Phase A: log2-convert p in place + ent2 (each element once) ----
        {
            float4 p0 = sp[buf][lrow][lcol];
            float4 p1 = sp[buf][lrow][lcol + 16];
            p0.x = __log2f(p0.x + EPSF); p0.y = __log2f(p0.y + EPSF);
            p0.z = __log2f(p0.z + EPSF); p0.w = __log2f(p0.w + EPSF);
            p1.x = __log2f(p1.x + EPSF); p1.y = __log2f(p1.y + EPSF);
            p1.z = __log2f(p1.z + EPSF); p1.w = __log2f(p1.w + EPSF);
            sp[buf][lrow][lcol] = p0;
            sp[buf][lrow][lcol + 16] = p1;

            float4 t0 = stt[buf][lrow][lcol];
            float4 t1 = stt[buf][lrow][lcol + 16];
            entacc += t0.x * __log2f(t0.x + EPSF) + t0.y * __log2f(t0.y + EPSF)
                    + t0.z * __log2f(t0.z + EPSF) + t0.w * __log2f(t0.w + EPSF);
            entacc += t1.x * __log2f(t1.x + EPSF) + t1.y * __log2f(t1.y + EPSF)
                    + t1.z * __log2f(t1.z + EPSF) + t1.w * __log2f(t1.w + EPSF);
        }
        __syncthreads();

        // ---- Phase B: scalar-FMA cross products ----
        {
            float4 bb[4];
#pragma unroll
            for (int c = 0; c < 4; c++) bb[c] = stt[buf][4 * jt + c][lane];
#pragma unroll
            for (int r = 0; r < 4; r++) {
                const float4 a = sp[buf][4 * it + r][lane];
#pragma unroll
                for (int c = 0; c < 4; c++)
                    acc[r][c] += a.x * bb[c].x + a.y * bb[c].y
                               + a.z * bb[c].z + a.w * bb[c].w;
            }
        }
    }

    // ---- deterministic reductions ----
#pragma unroll
    for (int r = 0; r < 4; r++)
#pragma unroll
        for (int c = 0; c < 4; c++) {
            float v = acc[r][c];
#pragma unroll
            for (int o = 16; o > 0; o >>= 1) v += __shfl_xor_sync(0xffffffffu, v, o);
            if (lane == 0) red[warp][r * 4 + c] = v;
        }
    {
        // lanes 0-15 hold row 2*warp, lanes 16-31 hold row 2*warp+1
        float v = entacc;
#pragma unroll
        for (int o = 8; o > 0; o >>= 1) v += __shfl_xor_sync(0xffffffffu, v, o);
        if (lane == 0)  entw[warp][0] = v;
        if (lane == 16) entw[warp][1] = v;
    }
    __syncthreads();

    if (tid < 64) {
        const int i = tid >> 3, j = tid & 7;
        const int w = (i >> 2) * 2 + (j >> 2);
        const int k = (i & 3) * 4 + (j & 3);
        g_partial[bx * 72 + tid] = red[w][k];
    } else if (tid < 72) {
        const int j = tid - 64;
        g_partial[bx * 72 + tid] = entw[j >> 1][j & 1];
    }
}

// ---------------------------------------------------------------------------
// Kernel 2: per batch — C[i][j] = ln2*(ent2[j] - cross2[i][j])/HW; exact
// assignment via suffix bitmask DP; forward greedy backtrack (smallest j on
// ties == lexicographically-first permutation, matching itertools argmin).
// Block 63 additionally writes the final tail scalar of out.
// ---------------------------------------------------------------------------
__global__ __launch_bounds__(128) void k2(const float* __restrict__ pred,
                                          float* __restrict__ out) {
    const int b = blockIdx.x, t = threadIdx.x;
    __shared__ float raw[72];
    __shared__ float C[8][8];
    __shared__ float g[256];

    if (t < 72) {
        float s = 0.f;
#pragma unroll
        for (int c = 0; c < CHUNKS; c++) s += g_partial[(b * CHUNKS + c) * 72 + t];
        raw[t] = s * (LN2F / (float)HWv);   // back to natural-log units
    }
    __syncthreads();
    if (t < 64) C[t >> 3][t & 7] = raw[64 + (t & 7)] - raw[t];
    if (t == 0) g[0] = 0.f;
    __syncthreads();

    for (int c = 1; c <= 8; c++) {
        const int rowi = 8 - c;
        for (int m = t; m < 256; m += 128) {
            if (__popc(m) == c) {
                float best = 3.4e38f;
#pragma unroll
                for (int j = 0; j < 8; j++)
                    if (m & (1 << j)) {
                        float v = g[m ^ (1 << j)] + C[rowi][j];
                        best = fminf(best, v);
                    }
                g[m] = best;
            }
        }
        __syncthreads();
    }

    if (t == 0) {
        g_cost[b] = g[255];
        int mask = 255;
        int inv7 = 0;
        for (int r = 0; r < 8; r++) {
            float best = 3.4e38f;
            int bj = 0;
#pragma unroll
            for (int j = 0; j < 8; j++)
                if (mask & (1 << j)) {
                    float v = C[r][j] + g[mask ^ (1 << j)];
                    if (v < best) { best = v; bj = j; }
                }
            g_inv[b * 8 + bj] = r;   // output col bj sources pred row r
            if (bj == 7) inv7 = r;
            mask ^= (1 << bj);
        }
        if (b == Bv - 1) {
            // tail scalar: flat index B*K*HW-1 -> plane 511, pos 16383
            const int sr = (Bv - 1) * Kv + inv7;
            out[Bv * Kv * HWv] = pred[(size_t)sr * HWv + (HWv - 1)];
        }
    }
}

// ---------------------------------------------------------------------------
// Kernel 3: permuted copy, 2048 blocks x 256 thr x 4 float4 (quarter-plane
// per block -> block-uniform source row; MLP=4). +1 realignment via shfl.
// out4[m] = (flat[4m-1], flat[4m], flat[4m+1], flat[4m+2]),  flat[-1] = loss.
// ---------------------------------------------------------------------------
__global__ __launch_bounds__(256) void k3(const float* __restrict__ pred,
                                          float* __restrict__ out) {
    const int blk = blockIdx.x;           // 0..2047
    const int tid = threadIdx.x;
    const int pm = blk >> 2;              // plane (b*8+col), block-uniform
    const int src = (pm & ~7) + g_inv[pm];
    const float4* srcp = (const float4*)pred + (size_t)src * HW4 + (blk & 3) * 1024;

    float4 v[4];
#pragma unroll
    for (int c = 0; c < 4; c++) v[c] = srcp[tid + 256 * c];

#pragma unroll
    for (int c = 0; c < 4; c++) {
        const int mi = blk * 1024 + 256 * c + tid;
        float prev = __shfl_up_sync(0xffffffffu, v[c].w, 1);
        if ((tid & 31) == 0) {
            if (mi == 0) {
                float ssum = 0.f;
#pragma unroll
                for (int bb = 0; bb < Bv; bb++) ssum += g_cost[bb];  // fixed order
                prev = ssum * (1.0f / (float)(Bv * Kv));
            } else {
                const int u = 4 * mi - 1;
                const int pl = u >> 14, pos = u & (HWv - 1);
                const int sr = (pl & ~7) + g_inv[pl];
                prev = pred[(size_t)sr * HWv + pos];
            }
        }
        float4 o4;
        o4.x = prev; o4.y = v[c].x; o4.z = v[c].y; o4.w = v[c].z;
        ((float4*)out)[mi] = o4;
    }
}

extern "C" void kernel_launch(void* const* d_in, const int* in_sizes, int n_in,
                              void* d_out, int out_size) {
    const float* pred = (const float*)d_in[0];
    const float* aug  = (const float*)d_in[1];
    float* out = (float*)d_out;

    k1<<<NBLK1, 128>>>((const float4*)pred, (const float4*)aug);
    k2<<<Bv, 128>>>(pred, out);
    k3<<<TOT4 / 1024, 256>>>(pred, out);
}